// round 12
// baseline (speedup 1.0000x reference)
#include <cuda_runtime.h>
#include <cuda_bf16.h>
#include <cstdint>

#define BB 512
#define LL 512
#define NN 128
#define EPITCH 132   // padded emission-stage pitch (floats)

__device__ float g_norm[BB];
__device__ float g_path[BB];

__device__ __forceinline__ uint32_t bfpack(float lo, float hi) {
    uint32_t d;
    asm("cvt.rn.bf16x2.f32 %0, %1, %2;" : "=r"(d) : "f"(hi), "f"(lo));
    return d;
}
__device__ __forceinline__ float frcp(float x) {
    float r;
    asm("rcp.approx.f32 %0, %1;" : "=f"(r) : "f"(x));
    return r;
}
__device__ __forceinline__ uint32_t movm(uint32_t x) {
    uint32_t d;
    asm("movmatrix.sync.aligned.m8n8.trans.b16 %0, %1;" : "=r"(d) : "r"(x));
    return d;
}
__device__ __forceinline__ void mma16816(float* d,
                                         uint32_t a0, uint32_t a1, uint32_t a2, uint32_t a3,
                                         uint32_t b0, uint32_t b1) {
    asm volatile("mma.sync.aligned.m16n8k16.row.col.f32.bf16.bf16.f32 "
                 "{%0,%1,%2,%3},{%4,%5,%6,%7},{%8,%9},{%0,%1,%2,%3};"
                 : "+f"(d[0]), "+f"(d[1]), "+f"(d[2]), "+f"(d[3])
                 : "r"(a0), "r"(a1), "r"(a2), "r"(a3), "r"(b0), "r"(b1));
}
__device__ __forceinline__ float blendq(float mk, float qc, float qold_inv) {
    if (mk == 1.0f) return qc;
    if (mk == 0.0f) return qold_inv;
    return __expf(mk * __logf(qc) + (1.0f - mk) * __logf(qold_inv));
}

// ---------------------------------------------------------------------------
// Forward: 64 blocks x 128 threads (4 warps). Block = 8 batches, ZERO padding.
// C[128 states x 8 batches] = E^T @ q; warp w owns m-tiles {2w, 2w+1}.
// A = E^T frags resident; next-step B frags via movmatrix + smem exchange.
// Emission staged TWO steps ahead (LDG t+2 / STS t+1 / read t) so DRAM
// latency never sits on the critical path. 4 MMA chains of depth 4.
// Linear-domain recurrence (stale-q0 shift); one __syncthreads per step.
// ---------------------------------------------------------------------------
__global__ __launch_bounds__(128, 1)
void crf_forward(const float* __restrict__ em,
                 const float* __restrict__ mask,
                 const float* __restrict__ start,
                 const float* __restrict__ trans) {
    __shared__ uint2 qfr[2][8][32];        // [parity][k-tile][lane]
    __shared__ float invsh[2][8];          // [parity][batch]
    __shared__ float esh[2][8][EPITCH];    // staged emission [parity][batch][state]
    __shared__ float msh[2][8];            // staged mask
    __shared__ float csh[8];
    __shared__ float ssum[4][8];

    const int tid  = threadIdx.x;
    const int w    = tid >> 5;             // warp 0..3 -> m-tiles 2w, 2w+1
    const int lane = tid & 31;
    const int r    = lane >> 2;
    const int c    = lane & 3;
    const int bA   = 2 * c, bB = bA + 1;   // this thread's 2 batches
    const int b0g  = blockIdx.x * 8;
    const bool wr  = (w == 0 && r == 0);   // writer lanes (state-0 holders)

    int S[2][2];
#pragma unroll
    for (int mi = 0; mi < 2; mi++) {
        S[mi][0] = 16 * (2 * w + mi) + r;
        S[mi][1] = S[mi][0] + 8;
    }

    // ---- A fragments: A[j][i] = exp(trans[i*128+j]), resident ----
    uint32_t Af[2][8][4];
#pragma unroll
    for (int mi = 0; mi < 2; mi++) {
        const int j0 = S[mi][0], j1 = S[mi][1];
#pragma unroll
        for (int kt = 0; kt < 8; kt++) {
            const int i0 = 16 * kt + 2 * c;
            Af[mi][kt][0] = bfpack(__expf(trans[(i0)     * NN + j0]),
                                   __expf(trans[(i0 + 1) * NN + j0]));
            Af[mi][kt][1] = bfpack(__expf(trans[(i0)     * NN + j1]),
                                   __expf(trans[(i0 + 1) * NN + j1]));
            Af[mi][kt][2] = bfpack(__expf(trans[(i0 + 8) * NN + j0]),
                                   __expf(trans[(i0 + 9) * NN + j0]));
            Af[mi][kt][3] = bfpack(__expf(trans[(i0 + 8) * NN + j1]),
                                   __expf(trans[(i0 + 9) * NN + j1]));
        }
    }

    const size_t ebA = (size_t)(b0g + bA) * (LL * NN);
    const size_t ebB = (size_t)(b0g + bB) * (LL * NN);

    // coalesced emission-stage role: batch lb, states ls..ls+7
    const int lb = tid >> 4, ls = (tid & 15) * 8;
    const float* eml = em + (size_t)(b0g + lb) * (LL * NN) + ls;

    float Lr_A = 0.f, Lr_B = 0.f;
    float qprev[2][2][2];                  // [mi][half][batch]

    // staged-emission registers: vS holds em[t+1] (STS'd during step t)
    float4 vS0, vS1;  float mvS = 1.0f;

    // ================= init t = 0 =================
    {
        float s0[2][2][2];
#pragma unroll
        for (int mi = 0; mi < 2; mi++)
#pragma unroll
            for (int h = 0; h < 2; h++) {
                const int s = S[mi][h];
                const float st = start[s];
                s0[mi][h][0] = st + em[ebA + s];
                s0[mi][h][1] = st + em[ebB + s];
            }
        if (wr) { csh[bA] = s0[0][0][0]; csh[bB] = s0[0][0][1]; }
        __syncthreads();
        const float cA = csh[bA], cB = csh[bB];
        Lr_A = cA; Lr_B = cB;
#pragma unroll
        for (int mi = 0; mi < 2; mi++)
#pragma unroll
            for (int h = 0; h < 2; h++) {
                qprev[mi][h][0] = __expf(s0[mi][h][0] - cA);
                qprev[mi][h][1] = __expf(s0[mi][h][1] - cB);
            }
        if (wr) {
            invsh[1][bA] = frcp(qprev[0][0][0]);
            invsh[1][bB] = frcp(qprev[0][0][1]);
        }
#pragma unroll
        for (int mi = 0; mi < 2; mi++) {
            uint32_t u0 = bfpack(qprev[mi][0][0], qprev[mi][0][1]);
            uint32_t u1 = bfpack(qprev[mi][1][0], qprev[mi][1][1]);
            qfr[1][2 * w + mi][lane] = make_uint2(movm(u0), movm(u1));
        }
        // stage em[1]/mask[1] directly; preload em[2]/mask[2] into registers
        *(float4*)&esh[1][lb][ls]     = *(const float4*)&eml[1 * NN];
        *(float4*)&esh[1][lb][ls + 4] = *(const float4*)&eml[1 * NN + 4];
        if (tid < 8) msh[1][tid] = mask[(size_t)(b0g + tid) * LL + 1];
        vS0 = *(const float4*)&eml[2 * NN];
        vS1 = *(const float4*)&eml[2 * NN + 4];
        if (tid < 8) mvS = mask[(size_t)(b0g + tid) * LL + 2];
        __syncthreads();
    }

    // ================= recurrence =================
    for (int t = 1; t < LL; t++) {
        const int pr = t & 1, pw = pr ^ 1;

        // ---- 0. LDG em[t+2] FIRST (lands ~2 steps later) ----
        float4 vN0 = make_float4(0.f, 0.f, 0.f, 0.f), vN1 = vN0;
        float mvN = 1.0f;
        if (t + 2 < LL) {
            vN0 = *(const float4*)&eml[(size_t)(t + 2) * NN];
            vN1 = *(const float4*)&eml[(size_t)(t + 2) * NN + 4];
            if (tid < 8) mvN = mask[(size_t)(b0g + tid) * LL + t + 2];
        }

        // ---- 1. STS staged em[t+1] / mask[t+1] (regs loaded at t-1) ----
        *(float4*)&esh[pw][lb][ls]     = vS0;
        *(float4*)&esh[pw][lb][ls + 4] = vS1;
        if (tid < 8) msh[pw][tid] = mvS;

        // ---- 2. B frags + inv + mask (written last step) ----
        uint2 bq[8];
#pragma unroll
        for (int kt = 0; kt < 8; kt++) bq[kt] = qfr[pr][kt][lane];
        const float invA = invsh[pr][bA];
        const float invB = invsh[pr][bB];
        const float mkA = msh[pr][bA];
        const float mkB = msh[pr][bB];

        // ---- 3. sc = exp(em[t]) * inv (MUFU, pre-MMA) ----
        float sc[2][2][2];
#pragma unroll
        for (int mi = 0; mi < 2; mi++)
#pragma unroll
            for (int h = 0; h < 2; h++) {
                sc[mi][h][0] = __expf(esh[pr][bA][S[mi][h]]) * invA;
                sc[mi][h][1] = __expf(esh[pr][bB][S[mi][h]]) * invB;
            }

        // ---- 4. MMA: 4 chains of depth 4 (even/odd k split) ----
        float C0e[4] = {0.f, 0.f, 0.f, 0.f};
        float C0o[4] = {0.f, 0.f, 0.f, 0.f};
        float C1e[4] = {0.f, 0.f, 0.f, 0.f};
        float C1o[4] = {0.f, 0.f, 0.f, 0.f};
#pragma unroll
        for (int kt = 0; kt < 8; kt += 2) {
            mma16816(C0e, Af[0][kt][0], Af[0][kt][1], Af[0][kt][2], Af[0][kt][3],
                     bq[kt].x, bq[kt].y);
            mma16816(C1e, Af[1][kt][0], Af[1][kt][1], Af[1][kt][2], Af[1][kt][3],
                     bq[kt].x, bq[kt].y);
            mma16816(C0o, Af[0][kt + 1][0], Af[0][kt + 1][1], Af[0][kt + 1][2], Af[0][kt + 1][3],
                     bq[kt + 1].x, bq[kt + 1].y);
            mma16816(C1o, Af[1][kt + 1][0], Af[1][kt + 1][1], Af[1][kt + 1][2], Af[1][kt + 1][3],
                     bq[kt + 1].x, bq[kt + 1].y);
        }

        // ---- 5. epilogue: scale, blend, recycle ----
        float qn[2][2][2];
        qn[0][0][0] = blendq(mkA, (C0e[0] + C0o[0]) * sc[0][0][0], qprev[0][0][0] * invA);
        qn[0][0][1] = blendq(mkB, (C0e[1] + C0o[1]) * sc[0][0][1], qprev[0][0][1] * invB);
        qn[0][1][0] = blendq(mkA, (C0e[2] + C0o[2]) * sc[0][1][0], qprev[0][1][0] * invA);
        qn[0][1][1] = blendq(mkB, (C0e[3] + C0o[3]) * sc[0][1][1], qprev[0][1][1] * invB);
        qn[1][0][0] = blendq(mkA, (C1e[0] + C1o[0]) * sc[1][0][0], qprev[1][0][0] * invA);
        qn[1][0][1] = blendq(mkB, (C1e[1] + C1o[1]) * sc[1][0][1], qprev[1][0][1] * invB);
        qn[1][1][0] = blendq(mkA, (C1e[2] + C1o[2]) * sc[1][1][0], qprev[1][1][0] * invA);
        qn[1][1][1] = blendq(mkB, (C1e[3] + C1o[3]) * sc[1][1][1], qprev[1][1][1] * invB);

        if (wr) {
            Lr_A -= __logf(invA);
            Lr_B -= __logf(invB);
            invsh[pw][bA] = frcp(qn[0][0][0]);
            invsh[pw][bB] = frcp(qn[0][0][1]);
        }
#pragma unroll
        for (int mi = 0; mi < 2; mi++) {
            uint32_t u0 = bfpack(qn[mi][0][0], qn[mi][0][1]);
            uint32_t u1 = bfpack(qn[mi][1][0], qn[mi][1][1]);
            qfr[pw][2 * w + mi][lane] = make_uint2(movm(u0), movm(u1));
#pragma unroll
            for (int h = 0; h < 2; h++) {
                qprev[mi][h][0] = qn[mi][h][0];
                qprev[mi][h][1] = qn[mi][h][1];
            }
        }

        // ---- 6. rotate staged-emission registers ----
        vS0 = vN0; vS1 = vN1; mvS = mvN;
        __syncthreads();
    }

    // ================= final logsumexp =================
    float sA = 0.f, sB = 0.f;
#pragma unroll
    for (int mi = 0; mi < 2; mi++)
#pragma unroll
        for (int h = 0; h < 2; h++) { sA += qprev[mi][h][0]; sB += qprev[mi][h][1]; }
#pragma unroll
    for (int o = 4; o <= 16; o <<= 1) {
        sA += __shfl_xor_sync(0xffffffffu, sA, o);
        sB += __shfl_xor_sync(0xffffffffu, sB, o);
    }
    if (r == 0) { ssum[w][bA] = sA; ssum[w][bB] = sB; }
    __syncthreads();
    if (wr) {
        float tA = ssum[0][bA] + ssum[1][bA] + ssum[2][bA] + ssum[3][bA];
        float tB = ssum[0][bB] + ssum[1][bB] + ssum[2][bB] + ssum[3][bB];
        g_norm[b0g + bA] = Lr_A + __logf(tA);
        g_norm[b0g + bB] = Lr_B + __logf(tB);
    }
}

// ---------------------------------------------------------------------------
// Path score. One block (128 threads) per batch.
// ---------------------------------------------------------------------------
__global__ __launch_bounds__(128)
void crf_path(const float* __restrict__ em,
              const int*   __restrict__ tgt,
              const float* __restrict__ mask,
              const float* __restrict__ start,
              const float* __restrict__ trans) {
    const int bb = blockIdx.x;
    const int tid = threadIdx.x;
    __shared__ float red[128];

    const size_t embase = (size_t)bb * LL * NN;
    float s = 0.0f;
    for (int t = tid; t < LL; t += 128) {
        if (t == 0) {
            int t0 = tgt[bb * LL];
            s += start[t0] + em[embase + t0];
        } else {
            int prev = tgt[bb * LL + t - 1];
            int cur  = tgt[bb * LL + t];
            s += mask[bb * LL + t] *
                 (trans[prev * NN + cur] + em[embase + (size_t)t * NN + cur]);
        }
    }
    red[tid] = s;
    __syncthreads();
#pragma unroll
    for (int o = 64; o; o >>= 1) {
        if (tid < o) red[tid] += red[tid + o];
        __syncthreads();
    }
    if (tid == 0) g_path[bb] = red[0];
}

// ---------------------------------------------------------------------------
// mean(normalizer - path)
// ---------------------------------------------------------------------------
__global__ __launch_bounds__(512)
void crf_final(float* __restrict__ out) {
    const int tid = threadIdx.x;
    __shared__ float wsum[16];
    float v = g_norm[tid] - g_path[tid];
#pragma unroll
    for (int o = 16; o; o >>= 1) v += __shfl_xor_sync(0xffffffffu, v, o);
    if ((tid & 31) == 0) wsum[tid >> 5] = v;
    __syncthreads();
    if (tid < 32) {
        float x = (tid < 16) ? wsum[tid] : 0.0f;
#pragma unroll
        for (int o = 8; o; o >>= 1) x += __shfl_xor_sync(0xffffffffu, x, o);
        if (tid == 0) out[0] = x * (1.0f / (float)BB);
    }
}

// ---------------------------------------------------------------------------
// Launch
// ---------------------------------------------------------------------------
extern "C" void kernel_launch(void* const* d_in, const int* in_sizes, int n_in,
                              void* d_out, int out_size) {
    const float* emission    = (const float*)d_in[0];
    const int*   target      = (const int*)  d_in[1];
    const float* mask        = (const float*)d_in[2];
    const float* start_trans = (const float*)d_in[3];
    const float* trans       = (const float*)d_in[4];
    float* out = (float*)d_out;

    crf_forward<<<64, 128>>>(emission, mask, start_trans, trans);
    crf_path<<<BB, 128>>>(emission, target, mask, start_trans, trans);
    crf_final<<<1, 512>>>(out);
}

// round 14
// speedup vs baseline: 1.1200x; 1.1200x over previous
#include <cuda_runtime.h>
#include <cuda_bf16.h>
#include <cstdint>

#define BB 512
#define LL 512
#define NN 128
#define EPITCH 132   // padded emission-stage pitch (floats)

__device__ float g_norm[BB];
__device__ float g_path[BB];

__device__ __forceinline__ uint32_t bfpack(float lo, float hi) {
    uint32_t d;
    asm("cvt.rn.bf16x2.f32 %0, %1, %2;" : "=r"(d) : "f"(hi), "f"(lo));
    return d;
}
__device__ __forceinline__ float frcp(float x) {
    float r;
    asm("rcp.approx.f32 %0, %1;" : "=f"(r) : "f"(x));
    return r;
}
__device__ __forceinline__ uint32_t movm(uint32_t x) {
    uint32_t d;
    asm("movmatrix.sync.aligned.m8n8.trans.b16 %0, %1;" : "=r"(d) : "r"(x));
    return d;
}
__device__ __forceinline__ void mma16816(float* d,
                                         uint32_t a0, uint32_t a1, uint32_t a2, uint32_t a3,
                                         uint32_t b0, uint32_t b1) {
    asm volatile("mma.sync.aligned.m16n8k16.row.col.f32.bf16.bf16.f32 "
                 "{%0,%1,%2,%3},{%4,%5,%6,%7},{%8,%9},{%0,%1,%2,%3};"
                 : "+f"(d[0]), "+f"(d[1]), "+f"(d[2]), "+f"(d[3])
                 : "r"(a0), "r"(a1), "r"(a2), "r"(a3), "r"(b0), "r"(b1));
}
__device__ __forceinline__ float blendq(float mk, float qc, float qold_inv) {
    if (mk == 1.0f) return qc;
    if (mk == 0.0f) return qold_inv;
    return __expf(mk * __logf(qc) + (1.0f - mk) * __logf(qold_inv));
}

// ---------------------------------------------------------------------------
// Forward: 64 blocks x 256 threads. Warps 0-3: COMPUTE (C = E^T @ q, warp w
// owns m-tiles {2w,2w+1}; A frags resident; next-step B frags via movmatrix
// + smem). Warps 4-7: PRODUCERS (stage exp(emission) + mask one step ahead;
// LDG runs 2 steps ahead). Compute warps' per-step instruction stream is
// minimal; producer issue fills compute stall bubbles on each SMSP.
// Linear-domain recurrence (stale-q0 shift); one __syncthreads per step.
// ---------------------------------------------------------------------------
__global__ __launch_bounds__(256, 1)
void crf_forward(const float* __restrict__ em,
                 const float* __restrict__ mask,
                 const float* __restrict__ start,
                 const float* __restrict__ trans) {
    __shared__ uint2 qfr[2][8][32];        // [parity][k-tile][lane]
    __shared__ float invsh[2][8];          // [parity][batch]
    __shared__ float esh[2][8][EPITCH];    // staged exp(emission) [par][batch][state]
    __shared__ float msh[2][8];            // staged mask
    __shared__ float csh[8];
    __shared__ float ssum[4][8];

    const int tid  = threadIdx.x;
    const int w    = tid >> 5;             // 0-3 compute, 4-7 producer
    const int lane = tid & 31;
    const int b0g  = blockIdx.x * 8;
    const bool isC = (w < 4);

    // ---------------- compute-warp identifiers ----------------
    const int r   = lane >> 2;
    const int c   = lane & 3;
    const int bA  = 2 * c, bB = bA + 1;
    const bool wr = (w == 0 && r == 0);
    int S[2][2];
#pragma unroll
    for (int mi = 0; mi < 2; mi++) {
        S[mi][0] = 16 * (2 * (w & 3) + mi) + r;
        S[mi][1] = S[mi][0] + 8;
    }

    // ---------------- producer identifiers ----------------
    const int ptid = tid - 128;                 // 0..127 for producers
    const int lb = (ptid >> 4) & 7;             // batch 0..7
    const int ls = (ptid & 15) * 8;             // 8 states per producer thread
    const float* eml = em + (size_t)(b0g + lb) * (LL * NN) + ls;

    // ---------------- A fragments (compute warps only) ----------------
    uint32_t Af[2][8][4];
    if (isC) {
#pragma unroll
        for (int mi = 0; mi < 2; mi++) {
            const int j0 = S[mi][0], j1 = S[mi][1];
#pragma unroll
            for (int kt = 0; kt < 8; kt++) {
                const int i0 = 16 * kt + 2 * c;
                Af[mi][kt][0] = bfpack(__expf(trans[(i0)     * NN + j0]),
                                       __expf(trans[(i0 + 1) * NN + j0]));
                Af[mi][kt][1] = bfpack(__expf(trans[(i0)     * NN + j1]),
                                       __expf(trans[(i0 + 1) * NN + j1]));
                Af[mi][kt][2] = bfpack(__expf(trans[(i0 + 8) * NN + j0]),
                                       __expf(trans[(i0 + 9) * NN + j0]));
                Af[mi][kt][3] = bfpack(__expf(trans[(i0 + 8) * NN + j1]),
                                       __expf(trans[(i0 + 9) * NN + j1]));
            }
        }
    }

    float Lr_A = 0.f, Lr_B = 0.f;
    float qprev[2][2][2];
    float4 vS0, vS1;              // producer: raw em[t+1] (exp'd at STS time)
    float  mvS = 1.0f;            // producer: mask[t+1]

    // ================= init =================
    {
        float s0[2][2][2];
        float4 e1a = make_float4(0,0,0,0), e1b = e1a;
        if (isC) {
            const size_t ebA = (size_t)(b0g + bA) * (LL * NN);
            const size_t ebB = (size_t)(b0g + bB) * (LL * NN);
#pragma unroll
            for (int mi = 0; mi < 2; mi++)
#pragma unroll
                for (int h = 0; h < 2; h++) {
                    const int s = S[mi][h];
                    const float st = start[s];
                    s0[mi][h][0] = st + em[ebA + s];
                    s0[mi][h][1] = st + em[ebB + s];
                }
            if (wr) { csh[bA] = s0[0][0][0]; csh[bB] = s0[0][0][1]; }
        } else {
            // producers: load em[1] (for esh[1]) and em[2] (for vS)
            e1a = *(const float4*)&eml[1 * NN];
            e1b = *(const float4*)&eml[1 * NN + 4];
            vS0 = *(const float4*)&eml[2 * NN];
            vS1 = *(const float4*)&eml[2 * NN + 4];
            if (ptid < 8) mvS = mask[(size_t)(b0g + ptid) * LL + 2];
        }
        __syncthreads();
        if (isC) {
            const float cA = csh[bA], cB = csh[bB];
            Lr_A = cA; Lr_B = cB;
#pragma unroll
            for (int mi = 0; mi < 2; mi++)
#pragma unroll
                for (int h = 0; h < 2; h++) {
                    qprev[mi][h][0] = __expf(s0[mi][h][0] - cA);
                    qprev[mi][h][1] = __expf(s0[mi][h][1] - cB);
                }
            if (wr) {
                invsh[1][bA] = frcp(qprev[0][0][0]);
                invsh[1][bB] = frcp(qprev[0][0][1]);
            }
#pragma unroll
            for (int mi = 0; mi < 2; mi++) {
                uint32_t u0 = bfpack(qprev[mi][0][0], qprev[mi][0][1]);
                uint32_t u1 = bfpack(qprev[mi][1][0], qprev[mi][1][1]);
                qfr[1][2 * w + mi][lane] = make_uint2(movm(u0), movm(u1));
            }
        } else {
            esh[1][lb][ls + 0] = __expf(e1a.x);
            esh[1][lb][ls + 1] = __expf(e1a.y);
            esh[1][lb][ls + 2] = __expf(e1a.z);
            esh[1][lb][ls + 3] = __expf(e1a.w);
            esh[1][lb][ls + 4] = __expf(e1b.x);
            esh[1][lb][ls + 5] = __expf(e1b.y);
            esh[1][lb][ls + 6] = __expf(e1b.z);
            esh[1][lb][ls + 7] = __expf(e1b.w);
            if (ptid < 8) msh[1][ptid] = mask[(size_t)(b0g + ptid) * LL + 1];
        }
        __syncthreads();
    }

    // ================= recurrence =================
    for (int t = 1; t < LL; t++) {
        const int pr = t & 1, pw = pr ^ 1;

        if (isC) {
            // ---- B frags + inv + mask (written last step) ----
            uint2 bq[8];
#pragma unroll
            for (int kt = 0; kt < 8; kt++) bq[kt] = qfr[pr][kt][lane];
            const float invA = invsh[pr][bA];
            const float invB = invsh[pr][bB];
            const float mkA = msh[pr][bA];
            const float mkB = msh[pr][bB];

            // ---- sc = staged exp(em[t]) * inv (LDS + FMUL only) ----
            float sc[2][2][2];
#pragma unroll
            for (int mi = 0; mi < 2; mi++)
#pragma unroll
                for (int h = 0; h < 2; h++) {
                    sc[mi][h][0] = esh[pr][bA][S[mi][h]] * invA;
                    sc[mi][h][1] = esh[pr][bB][S[mi][h]] * invB;
                }

            // ---- MMA: 4 chains of depth 4 ----
            float C0e[4] = {0.f, 0.f, 0.f, 0.f};
            float C0o[4] = {0.f, 0.f, 0.f, 0.f};
            float C1e[4] = {0.f, 0.f, 0.f, 0.f};
            float C1o[4] = {0.f, 0.f, 0.f, 0.f};
#pragma unroll
            for (int kt = 0; kt < 8; kt += 2) {
                mma16816(C0e, Af[0][kt][0], Af[0][kt][1], Af[0][kt][2], Af[0][kt][3],
                         bq[kt].x, bq[kt].y);
                mma16816(C1e, Af[1][kt][0], Af[1][kt][1], Af[1][kt][2], Af[1][kt][3],
                         bq[kt].x, bq[kt].y);
                mma16816(C0o, Af[0][kt+1][0], Af[0][kt+1][1], Af[0][kt+1][2], Af[0][kt+1][3],
                         bq[kt+1].x, bq[kt+1].y);
                mma16816(C1o, Af[1][kt+1][0], Af[1][kt+1][1], Af[1][kt+1][2], Af[1][kt+1][3],
                         bq[kt+1].x, bq[kt+1].y);
            }

            // ---- epilogue ----
            float qn[2][2][2];
            qn[0][0][0] = blendq(mkA, (C0e[0]+C0o[0]) * sc[0][0][0], qprev[0][0][0] * invA);
            qn[0][0][1] = blendq(mkB, (C0e[1]+C0o[1]) * sc[0][0][1], qprev[0][0][1] * invB);
            qn[0][1][0] = blendq(mkA, (C0e[2]+C0o[2]) * sc[0][1][0], qprev[0][1][0] * invA);
            qn[0][1][1] = blendq(mkB, (C0e[3]+C0o[3]) * sc[0][1][1], qprev[0][1][1] * invB);
            qn[1][0][0] = blendq(mkA, (C1e[0]+C1o[0]) * sc[1][0][0], qprev[1][0][0] * invA);
            qn[1][0][1] = blendq(mkB, (C1e[1]+C1o[1]) * sc[1][0][1], qprev[1][0][1] * invB);
            qn[1][1][0] = blendq(mkA, (C1e[2]+C1o[2]) * sc[1][1][0], qprev[1][1][0] * invA);
            qn[1][1][1] = blendq(mkB, (C1e[3]+C1o[3]) * sc[1][1][1], qprev[1][1][1] * invB);

            if (wr) {
                Lr_A -= __logf(invA);
                Lr_B -= __logf(invB);
                invsh[pw][bA] = frcp(qn[0][0][0]);
                invsh[pw][bB] = frcp(qn[0][0][1]);
            }
#pragma unroll
            for (int mi = 0; mi < 2; mi++) {
                uint32_t u0 = bfpack(qn[mi][0][0], qn[mi][0][1]);
                uint32_t u1 = bfpack(qn[mi][1][0], qn[mi][1][1]);
                qfr[pw][2 * w + mi][lane] = make_uint2(movm(u0), movm(u1));
#pragma unroll
                for (int h = 0; h < 2; h++) {
                    qprev[mi][h][0] = qn[mi][h][0];
                    qprev[mi][h][1] = qn[mi][h][1];
                }
            }
        } else {
            // ---- producer: stage exp(em[t+1]) from regs (loaded at t-1) ----
            esh[pw][lb][ls + 0] = __expf(vS0.x);
            esh[pw][lb][ls + 1] = __expf(vS0.y);
            esh[pw][lb][ls + 2] = __expf(vS0.z);
            esh[pw][lb][ls + 3] = __expf(vS0.w);
            esh[pw][lb][ls + 4] = __expf(vS1.x);
            esh[pw][lb][ls + 5] = __expf(vS1.y);
            esh[pw][lb][ls + 6] = __expf(vS1.z);
            esh[pw][lb][ls + 7] = __expf(vS1.w);
            if (ptid < 8) msh[pw][ptid] = mvS;

            // ---- LDG em[t+2] / mask[t+2] (2 steps ahead) ----
            if (t + 2 < LL) {
                vS0 = *(const float4*)&eml[(size_t)(t + 2) * NN];
                vS1 = *(const float4*)&eml[(size_t)(t + 2) * NN + 4];
                if (ptid < 8) mvS = mask[(size_t)(b0g + ptid) * LL + t + 2];
            } else {
                vS0 = make_float4(0.f, 0.f, 0.f, 0.f);
                vS1 = vS0;
                mvS = 1.0f;
            }
        }
        __syncthreads();
    }

    // ================= final logsumexp =================
    if (isC) {
        float sA = 0.f, sB = 0.f;
#pragma unroll
        for (int mi = 0; mi < 2; mi++)
#pragma unroll
            for (int h = 0; h < 2; h++) { sA += qprev[mi][h][0]; sB += qprev[mi][h][1]; }
#pragma unroll
        for (int o = 4; o <= 16; o <<= 1) {
            sA += __shfl_xor_sync(0xffffffffu, sA, o);
            sB += __shfl_xor_sync(0xffffffffu, sB, o);
        }
        if (r == 0) { ssum[w][bA] = sA; ssum[w][bB] = sB; }
    }
    __syncthreads();
    if (isC && wr) {
        float tA = ssum[0][bA] + ssum[1][bA] + ssum[2][bA] + ssum[3][bA];
        float tB = ssum[0][bB] + ssum[1][bB] + ssum[2][bB] + ssum[3][bB];
        g_norm[b0g + bA] = Lr_A + __logf(tA);
        g_norm[b0g + bB] = Lr_B + __logf(tB);
    }
}

// ---------------------------------------------------------------------------
// Path score. One block (128 threads) per batch.
// ---------------------------------------------------------------------------
__global__ __launch_bounds__(128)
void crf_path(const float* __restrict__ em,
              const int*   __restrict__ tgt,
              const float* __restrict__ mask,
              const float* __restrict__ start,
              const float* __restrict__ trans) {
    const int bb = blockIdx.x;
    const int tid = threadIdx.x;
    __shared__ float red[128];

    const size_t embase = (size_t)bb * LL * NN;
    float s = 0.0f;
    for (int t = tid; t < LL; t += 128) {
        if (t == 0) {
            int t0 = tgt[bb * LL];
            s += start[t0] + em[embase + t0];
        } else {
            int prev = tgt[bb * LL + t - 1];
            int cur  = tgt[bb * LL + t];
            s += mask[bb * LL + t] *
                 (trans[prev * NN + cur] + em[embase + (size_t)t * NN + cur]);
        }
    }
    red[tid] = s;
    __syncthreads();
#pragma unroll
    for (int o = 64; o; o >>= 1) {
        if (tid < o) red[tid] += red[tid + o];
        __syncthreads();
    }
    if (tid == 0) g_path[bb] = red[0];
}

// ---------------------------------------------------------------------------
// mean(normalizer - path)
// ---------------------------------------------------------------------------
__global__ __launch_bounds__(512)
void crf_final(float* __restrict__ out) {
    const int tid = threadIdx.x;
    __shared__ float wsum[16];
    float v = g_norm[tid] - g_path[tid];
#pragma unroll
    for (int o = 16; o; o >>= 1) v += __shfl_xor_sync(0xffffffffu, v, o);
    if ((tid & 31) == 0) wsum[tid >> 5] = v;
    __syncthreads();
    if (tid < 32) {
        float x = (tid < 16) ? wsum[tid] : 0.0f;
#pragma unroll
        for (int o = 8; o; o >>= 1) x += __shfl_xor_sync(0xffffffffu, x, o);
        if (tid == 0) out[0] = x * (1.0f / (float)BB);
    }
}

// ---------------------------------------------------------------------------
// Launch
// ---------------------------------------------------------------------------
extern "C" void kernel_launch(void* const* d_in, const int* in_sizes, int n_in,
                              void* d_out, int out_size) {
    const float* emission    = (const float*)d_in[0];
    const int*   target      = (const int*)  d_in[1];
    const float* mask        = (const float*)d_in[2];
    const float* start_trans = (const float*)d_in[3];
    const float* trans       = (const float*)d_in[4];
    float* out = (float*)d_out;

    crf_forward<<<64, 256>>>(emission, mask, start_trans, trans);
    crf_path<<<BB, 128>>>(emission, target, mask, start_trans, trans);
    crf_final<<<1, 512>>>(out);
}

// round 15
// speedup vs baseline: 1.1831x; 1.0563x over previous
#include <cuda_runtime.h>
#include <cuda_bf16.h>
#include <cstdint>

#define BB 512
#define LL 512
#define NN 128
#define EPITCH 132   // padded emission-stage pitch (floats)

__device__ float g_norm[BB];
__device__ float g_path[BB];

__device__ __forceinline__ uint32_t bfpack(float lo, float hi) {
    uint32_t d;
    asm("cvt.rn.bf16x2.f32 %0, %1, %2;" : "=r"(d) : "f"(hi), "f"(lo));
    return d;
}
__device__ __forceinline__ float frcp(float x) {
    float r;
    asm("rcp.approx.f32 %0, %1;" : "=f"(r) : "f"(x));
    return r;
}
__device__ __forceinline__ uint32_t movm(uint32_t x) {
    uint32_t d;
    asm("movmatrix.sync.aligned.m8n8.trans.b16 %0, %1;" : "=r"(d) : "r"(x));
    return d;
}
__device__ __forceinline__ void mma16816(float* d,
                                         uint32_t a0, uint32_t a1, uint32_t a2, uint32_t a3,
                                         uint32_t b0, uint32_t b1) {
    asm volatile("mma.sync.aligned.m16n8k16.row.col.f32.bf16.bf16.f32 "
                 "{%0,%1,%2,%3},{%4,%5,%6,%7},{%8,%9},{%0,%1,%2,%3};"
                 : "+f"(d[0]), "+f"(d[1]), "+f"(d[2]), "+f"(d[3])
                 : "r"(a0), "r"(a1), "r"(a2), "r"(a3), "r"(b0), "r"(b1));
}

// ---------------------------------------------------------------------------
// Forward: 64 blocks x 256 threads. Warps 0-3: COMPUTE; warps 4-7: PRODUCERS.
// Per-step stream is branch-free: blend = FSEL (binary masks exact), rare
// fractional-mask fallback behind one warp-uniform branch; writer block is
// 2 predicated STS; producer uses clamped indices. One __syncthreads/step.
// ---------------------------------------------------------------------------
__global__ __launch_bounds__(256, 1)
void crf_forward(const float* __restrict__ em,
                 const float* __restrict__ mask,
                 const float* __restrict__ start,
                 const float* __restrict__ trans) {
    __shared__ uint2 qfr[2][8][32];        // [parity][k-tile][lane]
    __shared__ float invsh[2][8];          // [parity][batch]
    __shared__ float esh[2][8][EPITCH];    // staged exp(emission)
    __shared__ float msh[2][8];            // staged mask
    __shared__ float csh[8];
    __shared__ float ssum[4][8];

    const int tid  = threadIdx.x;
    const int w    = tid >> 5;             // 0-3 compute, 4-7 producer
    const int lane = tid & 31;
    const int b0g  = blockIdx.x * 8;
    const bool isC = (w < 4);

    // compute-warp identifiers
    const int r   = lane >> 2;
    const int c   = lane & 3;
    const int bA  = 2 * c, bB = bA + 1;
    const bool wr = (w == 0 && r == 0);
    int S[2][2];
#pragma unroll
    for (int mi = 0; mi < 2; mi++) {
        S[mi][0] = 16 * (2 * (w & 3) + mi) + r;
        S[mi][1] = S[mi][0] + 8;
    }

    // producer identifiers
    const int ptid = tid - 128;
    const int lb = (ptid >> 4) & 7;
    const int ls = (ptid & 15) * 8;
    const float* eml = em + (size_t)(b0g + lb) * (LL * NN) + ls;
    const float* mkl = mask + (size_t)(b0g + lb) * LL;   // for lanes writing msh

    // A fragments (compute warps only)
    uint32_t Af[2][8][4];
    if (isC) {
#pragma unroll
        for (int mi = 0; mi < 2; mi++) {
            const int j0 = S[mi][0], j1 = S[mi][1];
#pragma unroll
            for (int kt = 0; kt < 8; kt++) {
                const int i0 = 16 * kt + 2 * c;
                Af[mi][kt][0] = bfpack(__expf(trans[(i0)     * NN + j0]),
                                       __expf(trans[(i0 + 1) * NN + j0]));
                Af[mi][kt][1] = bfpack(__expf(trans[(i0)     * NN + j1]),
                                       __expf(trans[(i0 + 1) * NN + j1]));
                Af[mi][kt][2] = bfpack(__expf(trans[(i0 + 8) * NN + j0]),
                                       __expf(trans[(i0 + 9) * NN + j0]));
                Af[mi][kt][3] = bfpack(__expf(trans[(i0 + 8) * NN + j1]),
                                       __expf(trans[(i0 + 9) * NN + j1]));
            }
        }
    }

    float Lr_A = 0.f, Lr_B = 0.f;
    float qprev[2][2][2];
    float4 vS0, vS1;
    float  mvS = 1.0f;

    // ================= init =================
    {
        float s0[2][2][2];
        float4 e1a = make_float4(0,0,0,0), e1b = e1a;
        if (isC) {
            const size_t ebA = (size_t)(b0g + bA) * (LL * NN);
            const size_t ebB = (size_t)(b0g + bB) * (LL * NN);
#pragma unroll
            for (int mi = 0; mi < 2; mi++)
#pragma unroll
                for (int h = 0; h < 2; h++) {
                    const int s = S[mi][h];
                    const float st = start[s];
                    s0[mi][h][0] = st + em[ebA + s];
                    s0[mi][h][1] = st + em[ebB + s];
                }
            if (wr) { csh[bA] = s0[0][0][0]; csh[bB] = s0[0][0][1]; }
        } else {
            e1a = *(const float4*)&eml[1 * NN];
            e1b = *(const float4*)&eml[1 * NN + 4];
            vS0 = *(const float4*)&eml[2 * NN];
            vS1 = *(const float4*)&eml[2 * NN + 4];
            mvS = mkl[2];
        }
        __syncthreads();
        if (isC) {
            const float cA = csh[bA], cB = csh[bB];
            Lr_A = cA; Lr_B = cB;
#pragma unroll
            for (int mi = 0; mi < 2; mi++)
#pragma unroll
                for (int h = 0; h < 2; h++) {
                    qprev[mi][h][0] = __expf(s0[mi][h][0] - cA);
                    qprev[mi][h][1] = __expf(s0[mi][h][1] - cB);
                }
            if (wr) {
                invsh[1][bA] = frcp(qprev[0][0][0]);
                invsh[1][bB] = frcp(qprev[0][0][1]);
            }
#pragma unroll
            for (int mi = 0; mi < 2; mi++) {
                uint32_t u0 = bfpack(qprev[mi][0][0], qprev[mi][0][1]);
                uint32_t u1 = bfpack(qprev[mi][1][0], qprev[mi][1][1]);
                qfr[1][2 * w + mi][lane] = make_uint2(movm(u0), movm(u1));
            }
        } else {
            esh[1][lb][ls + 0] = __expf(e1a.x);
            esh[1][lb][ls + 1] = __expf(e1a.y);
            esh[1][lb][ls + 2] = __expf(e1a.z);
            esh[1][lb][ls + 3] = __expf(e1a.w);
            esh[1][lb][ls + 4] = __expf(e1b.x);
            esh[1][lb][ls + 5] = __expf(e1b.y);
            esh[1][lb][ls + 6] = __expf(e1b.z);
            esh[1][lb][ls + 7] = __expf(e1b.w);
            if (ptid < 8) msh[1][ptid] = mask[(size_t)(b0g + ptid) * LL + 1];
        }
        __syncthreads();
    }

    // ================= recurrence =================
    for (int t = 1; t < LL; t++) {
        const int pr = t & 1, pw = pr ^ 1;

        if (isC) {
            // ---- inputs from last step ----
            uint2 bq[8];
#pragma unroll
            for (int kt = 0; kt < 8; kt++) bq[kt] = qfr[pr][kt][lane];
            const float invA = invsh[pr][bA];
            const float invB = invsh[pr][bB];
            const float mkA = msh[pr][bA];
            const float mkB = msh[pr][bB];

            float sc[2][2][2];
#pragma unroll
            for (int mi = 0; mi < 2; mi++)
#pragma unroll
                for (int h = 0; h < 2; h++) {
                    sc[mi][h][0] = esh[pr][bA][S[mi][h]] * invA;
                    sc[mi][h][1] = esh[pr][bB][S[mi][h]] * invB;
                }

            // ---- MMA: 4 chains of depth 4 ----
            float C0e[4] = {0.f,0.f,0.f,0.f}, C0o[4] = {0.f,0.f,0.f,0.f};
            float C1e[4] = {0.f,0.f,0.f,0.f}, C1o[4] = {0.f,0.f,0.f,0.f};
#pragma unroll
            for (int kt = 0; kt < 8; kt += 2) {
                mma16816(C0e, Af[0][kt][0], Af[0][kt][1], Af[0][kt][2], Af[0][kt][3],
                         bq[kt].x, bq[kt].y);
                mma16816(C1e, Af[1][kt][0], Af[1][kt][1], Af[1][kt][2], Af[1][kt][3],
                         bq[kt].x, bq[kt].y);
                mma16816(C0o, Af[0][kt+1][0], Af[0][kt+1][1], Af[0][kt+1][2], Af[0][kt+1][3],
                         bq[kt+1].x, bq[kt+1].y);
                mma16816(C1o, Af[1][kt+1][0], Af[1][kt+1][1], Af[1][kt+1][2], Af[1][kt+1][3],
                         bq[kt+1].x, bq[kt+1].y);
            }

            // ---- branch-free epilogue ----
            float qc[2][2][2], qold[2][2][2], qn[2][2][2];
            qc[0][0][0] = (C0e[0]+C0o[0]) * sc[0][0][0];
            qc[0][0][1] = (C0e[1]+C0o[1]) * sc[0][0][1];
            qc[0][1][0] = (C0e[2]+C0o[2]) * sc[0][1][0];
            qc[0][1][1] = (C0e[3]+C0o[3]) * sc[0][1][1];
            qc[1][0][0] = (C1e[0]+C1o[0]) * sc[1][0][0];
            qc[1][0][1] = (C1e[1]+C1o[1]) * sc[1][0][1];
            qc[1][1][0] = (C1e[2]+C1o[2]) * sc[1][1][0];
            qc[1][1][1] = (C1e[3]+C1o[3]) * sc[1][1][1];
#pragma unroll
            for (int mi = 0; mi < 2; mi++)
#pragma unroll
                for (int h = 0; h < 2; h++) {
                    qold[mi][h][0] = qprev[mi][h][0] * invA;
                    qold[mi][h][1] = qprev[mi][h][1] * invB;
                    qn[mi][h][0] = (mkA != 0.0f) ? qc[mi][h][0] : qold[mi][h][0];
                    qn[mi][h][1] = (mkB != 0.0f) ? qc[mi][h][1] : qold[mi][h][1];
                }

            // rare fractional-mask fallback (one uniform branch, never taken
            // for binary masks)
            const bool fracA = (mkA != 0.0f) && (mkA != 1.0f);
            const bool fracB = (mkB != 0.0f) && (mkB != 1.0f);
            if (__any_sync(0xffffffffu, fracA || fracB)) {
#pragma unroll
                for (int mi = 0; mi < 2; mi++)
#pragma unroll
                    for (int h = 0; h < 2; h++) {
                        qn[mi][h][0] = __expf(mkA * __logf(qc[mi][h][0]) +
                                              (1.f - mkA) * __logf(qold[mi][h][0]));
                        qn[mi][h][1] = __expf(mkB * __logf(qc[mi][h][1]) +
                                              (1.f - mkB) * __logf(qold[mi][h][1]));
                    }
            }

            // ---- log-offset + inverse (all lanes; 2 predicated STS) ----
            Lr_A -= __logf(invA);
            Lr_B -= __logf(invB);
            const float rA = frcp(qn[0][0][0]);
            const float rB = frcp(qn[0][0][1]);
            if (wr) {
                invsh[pw][bA] = rA;
                invsh[pw][bB] = rB;
            }

#pragma unroll
            for (int mi = 0; mi < 2; mi++) {
                uint32_t u0 = bfpack(qn[mi][0][0], qn[mi][0][1]);
                uint32_t u1 = bfpack(qn[mi][1][0], qn[mi][1][1]);
                qfr[pw][2 * w + mi][lane] = make_uint2(movm(u0), movm(u1));
#pragma unroll
                for (int h = 0; h < 2; h++) {
                    qprev[mi][h][0] = qn[mi][h][0];
                    qprev[mi][h][1] = qn[mi][h][1];
                }
            }
        } else {
            // ---- producer: stage exp(em[t+1]) (regs from t-1) ----
            esh[pw][lb][ls + 0] = __expf(vS0.x);
            esh[pw][lb][ls + 1] = __expf(vS0.y);
            esh[pw][lb][ls + 2] = __expf(vS0.z);
            esh[pw][lb][ls + 3] = __expf(vS0.w);
            esh[pw][lb][ls + 4] = __expf(vS1.x);
            esh[pw][lb][ls + 5] = __expf(vS1.y);
            esh[pw][lb][ls + 6] = __expf(vS1.z);
            esh[pw][lb][ls + 7] = __expf(vS1.w);
            if (ptid < 8) msh[pw][ptid] = mvS;

            // ---- LDG em[t+2] clamped (branch-free) ----
            const int tC = (t + 2 < LL) ? (t + 2) : (LL - 1);
            vS0 = *(const float4*)&eml[(size_t)tC * NN];
            vS1 = *(const float4*)&eml[(size_t)tC * NN + 4];
            mvS = mkl[tC];   // only lanes with ptid<8 consume their own value
        }
        __syncthreads();
    }

    // ================= final logsumexp =================
    if (isC) {
        float sA = 0.f, sB = 0.f;
#pragma unroll
        for (int mi = 0; mi < 2; mi++)
#pragma unroll
            for (int h = 0; h < 2; h++) { sA += qprev[mi][h][0]; sB += qprev[mi][h][1]; }
#pragma unroll
        for (int o = 4; o <= 16; o <<= 1) {
            sA += __shfl_xor_sync(0xffffffffu, sA, o);
            sB += __shfl_xor_sync(0xffffffffu, sB, o);
        }
        if (r == 0) { ssum[w][bA] = sA; ssum[w][bB] = sB; }
    }
    __syncthreads();
    if (isC && wr) {
        float tA = ssum[0][bA] + ssum[1][bA] + ssum[2][bA] + ssum[3][bA];
        float tB = ssum[0][bB] + ssum[1][bB] + ssum[2][bB] + ssum[3][bB];
        g_norm[b0g + bA] = Lr_A + __logf(tA);
        g_norm[b0g + bB] = Lr_B + __logf(tB);
    }
}

// ---------------------------------------------------------------------------
// Path score. One block (128 threads) per batch.
// ---------------------------------------------------------------------------
__global__ __launch_bounds__(128)
void crf_path(const float* __restrict__ em,
              const int*   __restrict__ tgt,
              const float* __restrict__ mask,
              const float* __restrict__ start,
              const float* __restrict__ trans) {
    const int bb = blockIdx.x;
    const int tid = threadIdx.x;
    __shared__ float red[128];

    const size_t embase = (size_t)bb * LL * NN;
    float s = 0.0f;
    for (int t = tid; t < LL; t += 128) {
        if (t == 0) {
            int t0 = tgt[bb * LL];
            s += start[t0] + em[embase + t0];
        } else {
            int prev = tgt[bb * LL + t - 1];
            int cur  = tgt[bb * LL + t];
            s += mask[bb * LL + t] *
                 (trans[prev * NN + cur] + em[embase + (size_t)t * NN + cur]);
        }
    }
    red[tid] = s;
    __syncthreads();
#pragma unroll
    for (int o = 64; o; o >>= 1) {
        if (tid < o) red[tid] += red[tid + o];
        __syncthreads();
    }
    if (tid == 0) g_path[bb] = red[0];
}

// ---------------------------------------------------------------------------
// mean(normalizer - path)
// ---------------------------------------------------------------------------
__global__ __launch_bounds__(512)
void crf_final(float* __restrict__ out) {
    const int tid = threadIdx.x;
    __shared__ float wsum[16];
    float v = g_norm[tid] - g_path[tid];
#pragma unroll
    for (int o = 16; o; o >>= 1) v += __shfl_xor_sync(0xffffffffu, v, o);
    if ((tid & 31) == 0) wsum[tid >> 5] = v;
    __syncthreads();
    if (tid < 32) {
        float x = (tid < 16) ? wsum[tid] : 0.0f;
#pragma unroll
        for (int o = 8; o; o >>= 1) x += __shfl_xor_sync(0xffffffffu, x, o);
        if (tid == 0) out[0] = x * (1.0f / (float)BB);
    }
}

// ---------------------------------------------------------------------------
// Launch
// ---------------------------------------------------------------------------
extern "C" void kernel_launch(void* const* d_in, const int* in_sizes, int n_in,
                              void* d_out, int out_size) {
    const float* emission    = (const float*)d_in[0];
    const int*   target      = (const int*)  d_in[1];
    const float* mask        = (const float*)d_in[2];
    const float* start_trans = (const float*)d_in[3];
    const float* trans       = (const float*)d_in[4];
    float* out = (float*)d_out;

    crf_forward<<<64, 256>>>(emission, mask, start_trans, trans);
    crf_path<<<BB, 128>>>(emission, target, mask, start_trans, trans);
    crf_final<<<1, 512>>>(out);
}